// round 1
// baseline (speedup 1.0000x reference)
#include <cuda_runtime.h>

// dims
#define B_ 64
#define N_ 32
#define F_ 16
#define S_ 8
#define C_ 128
#define H_ 256
#define D_ 256
#define OBS_STRIDE 9728
#define A_OFF 512        // N_*F_
#define E_OFF 1536       // N_*F_ + N_*N_
#define KAUG 4112        // (H_+1)*F_
#define ROWS 2048        // B_*N_
#define KSPLIT 16

// scratch (static device allocations; no runtime alloc)
__device__ __align__(16) float g_W2t[H_ * H_];        // W2 transposed [k][h]
__device__ __align__(16) float g_WkT[KAUG * C_];      // augmented Wk  [k=(h,f)][c]
__device__ __align__(16) float g_M[ROWS * KAUG];      // M[b*N+j][h*16+f]
__device__ __align__(16) float g_P[KSPLIT * ROWS * C_];

// ---------------------------------------------------------------------------
// Prep: transpose W2, build augmented WkT (Wk rows + bk row) in [k][c] layout
// ---------------------------------------------------------------------------
__global__ void prep_kernel(const float* __restrict__ W2,
                            const float* __restrict__ Wk,
                            const float* __restrict__ bk) {
    int t = blockIdx.x * blockDim.x + threadIdx.x;
    if (t < H_ * H_) {
        int k = t >> 8, h = t & 255;
        g_W2t[k * H_ + h] = W2[h * H_ + k];
    }
    if (t < KAUG * C_) {
        int k = t >> 7, c = t & 127;
        int h = k >> 4, f = k & 15;
        g_WkT[t] = (h < H_) ? Wk[h * (C_ * F_) + c * F_ + f] : bk[c * F_ + f];
    }
}

// ---------------------------------------------------------------------------
// Phase 1: per (b,j) row — compact active edges, edge MLP, accumulate
//   M[h][f] = sum_active_i h2[i][h] * X[b,i,f];   M[256][f] = sum_active_i X
// ---------------------------------------------------------------------------
__global__ void __launch_bounds__(256) phase1_kernel(
    const float* __restrict__ obs,
    const float* __restrict__ W1,
    const float* __restrict__ b1,
    const float* __restrict__ b2) {
    __shared__ __align__(16) float h1s[N_][H_];   // 32KB
    __shared__ __align__(16) float W1s[S_ * H_];  // 8KB
    __shared__ float b1s[H_];
    __shared__ __align__(16) float Xs[N_][F_];    // 2KB (zero-padded slots)
    __shared__ float Es[N_][S_];                  // 1KB
    __shared__ int actIdx[N_];
    __shared__ int s_nact;

    const int tid = threadIdx.x;
    const int row = blockIdx.x;
    const int b = row >> 5, j = row & 31;
    const float* orow = obs + (size_t)b * OBS_STRIDE;

    for (int t = tid; t < S_ * H_; t += 256) W1s[t] = W1[t];
    b1s[tid] = b1[tid];

    // deterministic compaction of active columns (warp 0)
    if (tid < 32) {
        float a = orow[A_OFF + j * N_ + tid];
        unsigned m = __ballot_sync(0xffffffffu, a != 0.0f);
        int pos = __popc(m & ((1u << tid) - 1u));
        if (a != 0.0f) actIdx[pos] = tid;
        if (tid == 0) s_nact = __popc(m);
    }
    __syncthreads();

    const int nact = s_nact;
    const int nslots = (nact + 7) & ~7;

    // gather X and E for active slots; zero padding
    for (int t = tid; t < N_ * F_; t += 256) {
        int e = t >> 4, f = t & 15;
        Xs[e][f] = (e < nact) ? orow[actIdx[e] * F_ + f] : 0.0f;
    }
    for (int t = tid; t < N_ * S_; t += 256) {
        int e = t >> 3, s = t & 7;
        Es[e][s] = (e < nact) ? orow[E_OFF + (j * N_ + actIdx[e]) * S_ + s] : 0.0f;
    }
    __syncthreads();

    const int k = tid;  // output unit index (H_ == 256 == blockDim)

    // h1 = relu(E @ W1 + b1) for all slots
    for (int e = 0; e < nslots; e++) {
        float acc = b1s[k];
#pragma unroll
        for (int s = 0; s < S_; s++) acc += Es[e][s] * W1s[s * H_ + k];
        h1s[e][k] = fmaxf(acc, 0.0f);
    }
    __syncthreads();

    // h2 = relu(h1 @ W2 + b2); fold into M on the fly
    float Mloc[F_];
#pragma unroll
    for (int f = 0; f < F_; f++) Mloc[f] = 0.0f;

    const float bk2 = b2[k];
    const float4* __restrict__ w2row =
        reinterpret_cast<const float4*>(g_W2t + (size_t)k * H_);

    for (int c0 = 0; c0 < nslots; c0 += 8) {
        float acc[8];
#pragma unroll
        for (int u = 0; u < 8; u++) acc[u] = bk2;
#pragma unroll 4
        for (int h4 = 0; h4 < H_ / 4; h4++) {
            float4 w = __ldg(&w2row[h4]);
#pragma unroll
            for (int u = 0; u < 8; u++) {
                float4 hv = *reinterpret_cast<const float4*>(&h1s[c0 + u][h4 * 4]);
                acc[u] += hv.x * w.x;
                acc[u] += hv.y * w.y;
                acc[u] += hv.z * w.z;
                acc[u] += hv.w * w.w;
            }
        }
#pragma unroll
        for (int u = 0; u < 8; u++) {
            float h2v = fmaxf(acc[u], 0.0f);
#pragma unroll
            for (int f = 0; f < F_; f++) Mloc[f] += h2v * Xs[c0 + u][f];
        }
    }

    // write M row for this k (16 floats)
    float* mrow = g_M + ((size_t)row * (H_ + 1) + k) * F_;
#pragma unroll
    for (int f = 0; f < F_; f += 4) {
        float4 v = make_float4(Mloc[f], Mloc[f + 1], Mloc[f + 2], Mloc[f + 3]);
        *reinterpret_cast<float4*>(mrow + f) = v;
    }

    // ones-row (bias-path aggregation): sum of active X
    if (tid < F_) {
        float s = 0.0f;
        for (int e = 0; e < N_; e++) s += Xs[e][tid];
        g_M[((size_t)row * (H_ + 1) + H_) * F_ + tid] = s;
    }
}

// ---------------------------------------------------------------------------
// Phase 2: split-K GEMM  P[s][2048][128] partials of  M[2048,4112] @ WkT[4112,128]
// tile: 128 rows x 128 cols x BK=16, 16x16 threads, 8x8 microtile
// ---------------------------------------------------------------------------
__global__ void __launch_bounds__(256) gemm_kernel() {
    __shared__ __align__(16) float As[16][132];  // transposed A tile (+pad)
    __shared__ __align__(16) float Bs[16][128];

    const int tid = threadIdx.x;
    const int tx = tid & 15, ty = tid >> 4;
    const int r0 = blockIdx.x * 128;
    const int s = blockIdx.y;

    float acc[8][8];
#pragma unroll
    for (int u = 0; u < 8; u++)
#pragma unroll
        for (int v = 0; v < 8; v++) acc[u][v] = 0.0f;

    for (int ch = s; ch < KAUG / 16; ch += KSPLIT) {
        const int k0 = ch * 16;
#pragma unroll
        for (int l = 0; l < 2; l++) {
            int t = tid + l * 256;
            int rr = t >> 2;
            int kk = (t & 3) << 2;
            float4 v = *reinterpret_cast<const float4*>(
                &g_M[(size_t)(r0 + rr) * KAUG + k0 + kk]);
            As[kk + 0][rr] = v.x;
            As[kk + 1][rr] = v.y;
            As[kk + 2][rr] = v.z;
            As[kk + 3][rr] = v.w;
        }
#pragma unroll
        for (int l = 0; l < 2; l++) {
            int t = tid + l * 256;
            int kk = t >> 5;
            int cc = (t & 31) << 2;
            *reinterpret_cast<float4*>(&Bs[kk][cc]) =
                *reinterpret_cast<const float4*>(&g_WkT[(size_t)(k0 + kk) * C_ + cc]);
        }
        __syncthreads();
#pragma unroll
        for (int kk = 0; kk < 16; kk++) {
            float4 a0 = *reinterpret_cast<const float4*>(&As[kk][ty * 8]);
            float4 a1 = *reinterpret_cast<const float4*>(&As[kk][ty * 8 + 4]);
            float4 b0 = *reinterpret_cast<const float4*>(&Bs[kk][tx * 8]);
            float4 b1 = *reinterpret_cast<const float4*>(&Bs[kk][tx * 8 + 4]);
            float av[8] = {a0.x, a0.y, a0.z, a0.w, a1.x, a1.y, a1.z, a1.w};
            float bv[8] = {b0.x, b0.y, b0.z, b0.w, b1.x, b1.y, b1.z, b1.w};
#pragma unroll
            for (int u = 0; u < 8; u++)
#pragma unroll
                for (int v = 0; v < 8; v++) acc[u][v] += av[u] * bv[v];
        }
        __syncthreads();
    }

    float* prow = g_P + ((size_t)s * ROWS + r0) * C_;
#pragma unroll
    for (int u = 0; u < 8; u++)
#pragma unroll
        for (int v = 0; v < 8; v += 4) {
            float4 o = make_float4(acc[u][v], acc[u][v + 1], acc[u][v + 2], acc[u][v + 3]);
            *reinterpret_cast<float4*>(&prow[(ty * 8 + u) * C_ + tx * 8 + v]) = o;
        }
}

// ---------------------------------------------------------------------------
// Phase 3: per batch element — reduce partials, + X@Wroot + bconv, relu,
// attention softmax pool, dense tanh
// ---------------------------------------------------------------------------
__global__ void __launch_bounds__(128) phase3_kernel(
    const float* __restrict__ obs,
    const float* __restrict__ Wroot,
    const float* __restrict__ bconv,
    const float* __restrict__ attn_w,
    const float* __restrict__ Wd,
    const float* __restrict__ bd,
    float* __restrict__ out) {
    __shared__ float Xc[N_][C_];
    __shared__ float Wroots[F_ * C_];
    __shared__ float attn[N_];
    __shared__ float logits[N_];
    __shared__ float pooled[C_];

    const int b = blockIdx.x;
    const int tid = threadIdx.x;  // 128 == C_
    const float* orow = obs + (size_t)b * OBS_STRIDE;

    for (int t = tid; t < F_ * C_; t += 128) Wroots[t] = Wroot[t];
    __syncthreads();

    const int c = tid;
    const float bc = bconv[c];
    for (int j = 0; j < N_; j++) {
        const int row = b * N_ + j;
        float sum = bc;
#pragma unroll
        for (int ks = 0; ks < KSPLIT; ks++)
            sum += g_P[((size_t)ks * ROWS + row) * C_ + c];
#pragma unroll
        for (int f = 0; f < F_; f++) sum += orow[j * F_ + f] * Wroots[f * C_ + c];
        Xc[j][c] = fmaxf(sum, 0.0f);
    }
    __syncthreads();

    // attention logits: 4 warps x 8 nodes each
    const int w = tid >> 5, lane = tid & 31;
    const float aw0 = attn_w[lane], aw1 = attn_w[lane + 32];
    const float aw2 = attn_w[lane + 64], aw3 = attn_w[lane + 96];
    for (int j = w * 8; j < w * 8 + 8; j++) {
        float p = Xc[j][lane] * aw0 + Xc[j][lane + 32] * aw1 +
                  Xc[j][lane + 64] * aw2 + Xc[j][lane + 96] * aw3;
#pragma unroll
        for (int off = 16; off; off >>= 1) p += __shfl_xor_sync(0xffffffffu, p, off);
        if (lane == 0) logits[j] = p;
    }
    __syncthreads();

    if (tid < 32) {
        float l = logits[tid];
        float m = l;
#pragma unroll
        for (int off = 16; off; off >>= 1)
            m = fmaxf(m, __shfl_xor_sync(0xffffffffu, m, off));
        float e = expf(l - m);
        float ssum = e;
#pragma unroll
        for (int off = 16; off; off >>= 1) ssum += __shfl_xor_sync(0xffffffffu, ssum, off);
        attn[tid] = e / ssum;
    }
    __syncthreads();

    float pc = 0.0f;
#pragma unroll
    for (int j = 0; j < N_; j++) pc += attn[j] * Xc[j][c];
    pooled[c] = pc;
    __syncthreads();

    for (int d0 = tid; d0 < D_; d0 += 128) {
        float sum = bd[d0];
#pragma unroll 8
        for (int cc = 0; cc < C_; cc++) sum += pooled[cc] * Wd[cc * D_ + d0];
        out[b * D_ + d0] = tanhf(sum);
    }
}

// ---------------------------------------------------------------------------
extern "C" void kernel_launch(void* const* d_in, const int* in_sizes, int n_in,
                              void* d_out, int out_size) {
    const float* obs    = (const float*)d_in[0];
    const float* W1     = (const float*)d_in[1];
    const float* b1     = (const float*)d_in[2];
    const float* W2     = (const float*)d_in[3];
    const float* b2     = (const float*)d_in[4];
    const float* Wk     = (const float*)d_in[5];
    const float* bk     = (const float*)d_in[6];
    const float* Wroot  = (const float*)d_in[7];
    const float* bconv  = (const float*)d_in[8];
    const float* attn_w = (const float*)d_in[9];
    const float* Wd     = (const float*)d_in[10];
    const float* bd     = (const float*)d_in[11];
    float* out = (float*)d_out;

    prep_kernel<<<(KAUG * C_ + 255) / 256, 256>>>(W2, Wk, bk);
    phase1_kernel<<<ROWS, 256>>>(obs, W1, b1, b2);
    gemm_kernel<<<dim3(ROWS / 128, KSPLIT), 256>>>();
    phase3_kernel<<<B_, 128>>>(obs, Wroot, bconv, attn_w, Wd, bd, out);
}

// round 2
// speedup vs baseline: 1.0002x; 1.0002x over previous
#include <cuda_runtime.h>

// dims
#define B_ 64
#define N_ 32
#define F_ 16
#define S_ 8
#define C_ 128
#define H_ 256
#define D_ 256
#define OBS_STRIDE 9728
#define A_OFF 512        // N_*F_
#define E_OFF 1536       // N_*F_ + N_*N_
#define KAUG 4112        // (H_+1)*F_
#define ROWS 2048        // B_*N_
#define KSPLIT 16

// scratch (static device allocations; no runtime alloc)
__device__ __align__(16) float g_W2t[H_ * H_];        // W2 transposed [k][h]
__device__ __align__(16) float g_WkT[KAUG * C_];      // augmented Wk  [k=(h,f)][c]
__device__ __align__(16) float g_M[ROWS * KAUG];      // M[b*N+j][h*16+f]
__device__ __align__(16) float g_P[KSPLIT * ROWS * C_];

// ---------------------------------------------------------------------------
// Prep: transpose W2, build augmented WkT (Wk rows + bk row) in [k][c] layout
// ---------------------------------------------------------------------------
__global__ void prep_kernel(const float* __restrict__ W2,
                            const float* __restrict__ Wk,
                            const float* __restrict__ bk) {
    int t = blockIdx.x * blockDim.x + threadIdx.x;
    if (t < H_ * H_) {
        int k = t >> 8, h = t & 255;
        g_W2t[k * H_ + h] = W2[h * H_ + k];
    }
    if (t < KAUG * C_) {
        int k = t >> 7, c = t & 127;
        int h = k >> 4, f = k & 15;
        g_WkT[t] = (h < H_) ? Wk[h * (C_ * F_) + c * F_ + f] : bk[c * F_ + f];
    }
}

// ---------------------------------------------------------------------------
// Phase 1: per (b,j) row — compact active edges, edge MLP, accumulate
//   M[h][f] = sum_active_i h2[i][h] * X[b,i,f];   M[256][f] = sum_active_i X
// ---------------------------------------------------------------------------
__global__ void __launch_bounds__(256) phase1_kernel(
    const float* __restrict__ obs,
    const float* __restrict__ W1,
    const float* __restrict__ b1,
    const float* __restrict__ b2) {
    __shared__ __align__(16) float h1s[N_][H_];   // 32KB
    __shared__ __align__(16) float W1s[S_ * H_];  // 8KB
    __shared__ float b1s[H_];
    __shared__ __align__(16) float Xs[N_][F_];    // 2KB (zero-padded slots)
    __shared__ float Es[N_][S_];                  // 1KB
    __shared__ int actIdx[N_];
    __shared__ int s_nact;

    const int tid = threadIdx.x;
    const int row = blockIdx.x;
    const int b = row >> 5, j = row & 31;
    const float* orow = obs + (size_t)b * OBS_STRIDE;

    for (int t = tid; t < S_ * H_; t += 256) W1s[t] = W1[t];
    b1s[tid] = b1[tid];

    // deterministic compaction of active columns (warp 0)
    if (tid < 32) {
        float a = orow[A_OFF + j * N_ + tid];
        unsigned m = __ballot_sync(0xffffffffu, a != 0.0f);
        int pos = __popc(m & ((1u << tid) - 1u));
        if (a != 0.0f) actIdx[pos] = tid;
        if (tid == 0) s_nact = __popc(m);
    }
    __syncthreads();

    const int nact = s_nact;
    const int nslots = (nact + 7) & ~7;

    // gather X and E for active slots; zero padding
    for (int t = tid; t < N_ * F_; t += 256) {
        int e = t >> 4, f = t & 15;
        Xs[e][f] = (e < nact) ? orow[actIdx[e] * F_ + f] : 0.0f;
    }
    for (int t = tid; t < N_ * S_; t += 256) {
        int e = t >> 3, s = t & 7;
        Es[e][s] = (e < nact) ? orow[E_OFF + (j * N_ + actIdx[e]) * S_ + s] : 0.0f;
    }
    __syncthreads();

    const int k = tid;  // output unit index (H_ == 256 == blockDim)

    // h1 = relu(E @ W1 + b1) for all slots
    for (int e = 0; e < nslots; e++) {
        float acc = b1s[k];
#pragma unroll
        for (int s = 0; s < S_; s++) acc += Es[e][s] * W1s[s * H_ + k];
        h1s[e][k] = fmaxf(acc, 0.0f);
    }
    __syncthreads();

    // h2 = relu(h1 @ W2 + b2); fold into M on the fly
    float Mloc[F_];
#pragma unroll
    for (int f = 0; f < F_; f++) Mloc[f] = 0.0f;

    const float bk2 = b2[k];
    const float4* __restrict__ w2row =
        reinterpret_cast<const float4*>(g_W2t + (size_t)k * H_);

    for (int c0 = 0; c0 < nslots; c0 += 8) {
        float acc[8];
#pragma unroll
        for (int u = 0; u < 8; u++) acc[u] = bk2;
#pragma unroll 4
        for (int h4 = 0; h4 < H_ / 4; h4++) {
            float4 w = __ldg(&w2row[h4]);
#pragma unroll
            for (int u = 0; u < 8; u++) {
                float4 hv = *reinterpret_cast<const float4*>(&h1s[c0 + u][h4 * 4]);
                acc[u] += hv.x * w.x;
                acc[u] += hv.y * w.y;
                acc[u] += hv.z * w.z;
                acc[u] += hv.w * w.w;
            }
        }
#pragma unroll
        for (int u = 0; u < 8; u++) {
            float h2v = fmaxf(acc[u], 0.0f);
#pragma unroll
            for (int f = 0; f < F_; f++) Mloc[f] += h2v * Xs[c0 + u][f];
        }
    }

    // write M row for this k (16 floats)
    float* mrow = g_M + ((size_t)row * (H_ + 1) + k) * F_;
#pragma unroll
    for (int f = 0; f < F_; f += 4) {
        float4 v = make_float4(Mloc[f], Mloc[f + 1], Mloc[f + 2], Mloc[f + 3]);
        *reinterpret_cast<float4*>(mrow + f) = v;
    }

    // ones-row (bias-path aggregation): sum of active X
    if (tid < F_) {
        float s = 0.0f;
        for (int e = 0; e < N_; e++) s += Xs[e][tid];
        g_M[((size_t)row * (H_ + 1) + H_) * F_ + tid] = s;
    }
}

// ---------------------------------------------------------------------------
// Phase 2: split-K GEMM  P[s][2048][128] partials of  M[2048,4112] @ WkT[4112,128]
// tile: 128 rows x 128 cols x BK=16, 16x16 threads, 8x8 microtile
// ---------------------------------------------------------------------------
__global__ void __launch_bounds__(256) gemm_kernel() {
    __shared__ __align__(16) float As[16][132];  // transposed A tile (+pad)
    __shared__ __align__(16) float Bs[16][128];

    const int tid = threadIdx.x;
    const int tx = tid & 15, ty = tid >> 4;
    const int r0 = blockIdx.x * 128;
    const int s = blockIdx.y;

    float acc[8][8];
#pragma unroll
    for (int u = 0; u < 8; u++)
#pragma unroll
        for (int v = 0; v < 8; v++) acc[u][v] = 0.0f;

    for (int ch = s; ch < KAUG / 16; ch += KSPLIT) {
        const int k0 = ch * 16;
#pragma unroll
        for (int l = 0; l < 2; l++) {
            int t = tid + l * 256;
            int rr = t >> 2;
            int kk = (t & 3) << 2;
            float4 v = *reinterpret_cast<const float4*>(
                &g_M[(size_t)(r0 + rr) * KAUG + k0 + kk]);
            As[kk + 0][rr] = v.x;
            As[kk + 1][rr] = v.y;
            As[kk + 2][rr] = v.z;
            As[kk + 3][rr] = v.w;
        }
#pragma unroll
        for (int l = 0; l < 2; l++) {
            int t = tid + l * 256;
            int kk = t >> 5;
            int cc = (t & 31) << 2;
            *reinterpret_cast<float4*>(&Bs[kk][cc]) =
                *reinterpret_cast<const float4*>(&g_WkT[(size_t)(k0 + kk) * C_ + cc]);
        }
        __syncthreads();
#pragma unroll
        for (int kk = 0; kk < 16; kk++) {
            float4 a0 = *reinterpret_cast<const float4*>(&As[kk][ty * 8]);
            float4 a1 = *reinterpret_cast<const float4*>(&As[kk][ty * 8 + 4]);
            float4 b0 = *reinterpret_cast<const float4*>(&Bs[kk][tx * 8]);
            float4 b1 = *reinterpret_cast<const float4*>(&Bs[kk][tx * 8 + 4]);
            float av[8] = {a0.x, a0.y, a0.z, a0.w, a1.x, a1.y, a1.z, a1.w};
            float bv[8] = {b0.x, b0.y, b0.z, b0.w, b1.x, b1.y, b1.z, b1.w};
#pragma unroll
            for (int u = 0; u < 8; u++)
#pragma unroll
                for (int v = 0; v < 8; v++) acc[u][v] += av[u] * bv[v];
        }
        __syncthreads();
    }

    float* prow = g_P + ((size_t)s * ROWS + r0) * C_;
#pragma unroll
    for (int u = 0; u < 8; u++)
#pragma unroll
        for (int v = 0; v < 8; v += 4) {
            float4 o = make_float4(acc[u][v], acc[u][v + 1], acc[u][v + 2], acc[u][v + 3]);
            *reinterpret_cast<float4*>(&prow[(ty * 8 + u) * C_ + tx * 8 + v]) = o;
        }
}

// ---------------------------------------------------------------------------
// Phase 3: per batch element — reduce partials, + X@Wroot + bconv, relu,
// attention softmax pool, dense tanh
// ---------------------------------------------------------------------------
__global__ void __launch_bounds__(128) phase3_kernel(
    const float* __restrict__ obs,
    const float* __restrict__ Wroot,
    const float* __restrict__ bconv,
    const float* __restrict__ attn_w,
    const float* __restrict__ Wd,
    const float* __restrict__ bd,
    float* __restrict__ out) {
    __shared__ float Xc[N_][C_];
    __shared__ float Wroots[F_ * C_];
    __shared__ float attn[N_];
    __shared__ float logits[N_];
    __shared__ float pooled[C_];

    const int b = blockIdx.x;
    const int tid = threadIdx.x;  // 128 == C_
    const float* orow = obs + (size_t)b * OBS_STRIDE;

    for (int t = tid; t < F_ * C_; t += 128) Wroots[t] = Wroot[t];
    __syncthreads();

    const int c = tid;
    const float bc = bconv[c];
    for (int j = 0; j < N_; j++) {
        const int row = b * N_ + j;
        float sum = bc;
#pragma unroll
        for (int ks = 0; ks < KSPLIT; ks++)
            sum += g_P[((size_t)ks * ROWS + row) * C_ + c];
#pragma unroll
        for (int f = 0; f < F_; f++) sum += orow[j * F_ + f] * Wroots[f * C_ + c];
        Xc[j][c] = fmaxf(sum, 0.0f);
    }
    __syncthreads();

    // attention logits: 4 warps x 8 nodes each
    const int w = tid >> 5, lane = tid & 31;
    const float aw0 = attn_w[lane], aw1 = attn_w[lane + 32];
    const float aw2 = attn_w[lane + 64], aw3 = attn_w[lane + 96];
    for (int j = w * 8; j < w * 8 + 8; j++) {
        float p = Xc[j][lane] * aw0 + Xc[j][lane + 32] * aw1 +
                  Xc[j][lane + 64] * aw2 + Xc[j][lane + 96] * aw3;
#pragma unroll
        for (int off = 16; off; off >>= 1) p += __shfl_xor_sync(0xffffffffu, p, off);
        if (lane == 0) logits[j] = p;
    }
    __syncthreads();

    if (tid < 32) {
        float l = logits[tid];
        float m = l;
#pragma unroll
        for (int off = 16; off; off >>= 1)
            m = fmaxf(m, __shfl_xor_sync(0xffffffffu, m, off));
        float e = expf(l - m);
        float ssum = e;
#pragma unroll
        for (int off = 16; off; off >>= 1) ssum += __shfl_xor_sync(0xffffffffu, ssum, off);
        attn[tid] = e / ssum;
    }
    __syncthreads();

    float pc = 0.0f;
#pragma unroll
    for (int j = 0; j < N_; j++) pc += attn[j] * Xc[j][c];
    pooled[c] = pc;
    __syncthreads();

    for (int d0 = tid; d0 < D_; d0 += 128) {
        float sum = bd[d0];
#pragma unroll 8
        for (int cc = 0; cc < C_; cc++) sum += pooled[cc] * Wd[cc * D_ + d0];
        out[b * D_ + d0] = tanhf(sum);
    }
}

// ---------------------------------------------------------------------------
extern "C" void kernel_launch(void* const* d_in, const int* in_sizes, int n_in,
                              void* d_out, int out_size) {
    const float* obs    = (const float*)d_in[0];
    const float* W1     = (const float*)d_in[1];
    const float* b1     = (const float*)d_in[2];
    const float* W2     = (const float*)d_in[3];
    const float* b2     = (const float*)d_in[4];
    const float* Wk     = (const float*)d_in[5];
    const float* bk     = (const float*)d_in[6];
    const float* Wroot  = (const float*)d_in[7];
    const float* bconv  = (const float*)d_in[8];
    const float* attn_w = (const float*)d_in[9];
    const float* Wd     = (const float*)d_in[10];
    const float* bd     = (const float*)d_in[11];
    float* out = (float*)d_out;

    prep_kernel<<<(KAUG * C_ + 255) / 256, 256>>>(W2, Wk, bk);
    phase1_kernel<<<ROWS, 256>>>(obs, W1, b1, b2);
    gemm_kernel<<<dim3(ROWS / 128, KSPLIT), 256>>>();
    phase3_kernel<<<B_, 128>>>(obs, Wroot, bconv, attn_w, Wd, bd, out);
}

// round 3
// speedup vs baseline: 1.3186x; 1.3184x over previous
#include <cuda_runtime.h>

// dims
#define B_ 64
#define N_ 32
#define F_ 16
#define S_ 8
#define C_ 128
#define H_ 256
#define D_ 256
#define OBS_STRIDE 9728
#define A_OFF 512        // N_*F_
#define E_OFF 1536       // N_*F_ + N_*N_
#define KAUG 4112        // (H_+1)*F_
#define ROWS 2048        // B_*N_
#define KSPLIT 16

// scratch (static device allocations; no runtime alloc)
__device__ __align__(16) float g_WkT[KAUG * C_];      // augmented Wk  [k=(h,f)][c]
__device__ __align__(16) float g_M[ROWS * KAUG];      // M[b*N+j][h*16+f]
__device__ __align__(16) float g_P[KSPLIT * ROWS * C_];
__device__ __align__(16) float g_Xc[ROWS * C_];       // post-conv node features

// ---------------------------------------------------------------------------
// Prep: build augmented WkT (Wk rows + bk row) in [k][c] layout
// ---------------------------------------------------------------------------
__global__ void prep_kernel(const float* __restrict__ Wk,
                            const float* __restrict__ bk) {
    int t = blockIdx.x * blockDim.x + threadIdx.x;
    if (t < KAUG * C_) {
        int k = t >> 7, c = t & 127;
        int h = k >> 4, f = k & 15;
        g_WkT[t] = (h < H_) ? Wk[h * (C_ * F_) + c * F_ + f] : bk[c * F_ + f];
    }
}

// ---------------------------------------------------------------------------
// Phase 1: per (b,j) row — compact active edges, edge MLP, accumulate
//   M[h][f] = sum_active_i h2[i][h] * X[b,i,f];   M[256][f] = sum_active_i X
// W2 is streamed through smem in [h][k] chunks of 32 h (coalesced LDG,
// conflict-free LDS) — removes the 32-line-per-LDG pattern of round 1.
// h2 partials accumulate in a smem buffer across chunks.
// Dynamic smem layout (floats):
//   h1s  [32][256]  @ 0
//   h2s  [32][256]  @ 8192
//   W2s  [32][256]  @ 16384
//   W1s  [8][256]   @ 24576
//   b1s  [256]      @ 26624
//   Xs   [32][16]   @ 26880
//   Es   [32][8]    @ 27392      total 27648 floats = 110592 B
// ---------------------------------------------------------------------------
#define P1_SMEM_BYTES (27648 * 4)

__global__ void __launch_bounds__(256) phase1_kernel(
    const float* __restrict__ obs,
    const float* __restrict__ W1,
    const float* __restrict__ b1,
    const float* __restrict__ W2,
    const float* __restrict__ b2) {
    extern __shared__ __align__(16) float sm[];
    float* h1s = sm;
    float* h2s = sm + 8192;
    float* W2s = sm + 16384;
    float* W1s = sm + 24576;
    float* b1s = sm + 26624;
    float* Xs  = sm + 26880;
    float* Es  = sm + 27392;
    __shared__ int actIdx[N_];
    __shared__ int s_nact;

    const int tid = threadIdx.x;
    const int row = blockIdx.x;
    const int b = row >> 5, j = row & 31;
    const float* orow = obs + (size_t)b * OBS_STRIDE;

    for (int t = tid; t < S_ * H_; t += 256) W1s[t] = W1[t];
    b1s[tid] = b1[tid];

    // deterministic compaction of active columns (warp 0)
    if (tid < 32) {
        float a = orow[A_OFF + j * N_ + tid];
        unsigned m = __ballot_sync(0xffffffffu, a != 0.0f);
        int pos = __popc(m & ((1u << tid) - 1u));
        if (a != 0.0f) actIdx[pos] = tid;
        if (tid == 0) s_nact = __popc(m);
    }
    __syncthreads();

    const int nact = s_nact;
    const int nslots = (nact + 7) & ~7;

    // gather X and E for active slots; zero padding (zero X => padded slots
    // contribute nothing to M even though their h1/h2 are nonzero)
    for (int t = tid; t < N_ * F_; t += 256) {
        int e = t >> 4, f = t & 15;
        Xs[e * F_ + f] = (e < nact) ? orow[actIdx[e] * F_ + f] : 0.0f;
    }
    for (int t = tid; t < N_ * S_; t += 256) {
        int e = t >> 3, s = t & 7;
        Es[e * S_ + s] = (e < nact) ? orow[E_OFF + (j * N_ + actIdx[e]) * S_ + s] : 0.0f;
    }
    __syncthreads();

    const int k = tid;  // output unit index (H_ == 256 == blockDim)

    // h1 = relu(E @ W1 + b1) for all slots; zero-init h2 accumulator
    for (int e = 0; e < nslots; e++) {
        float acc = b1s[k];
#pragma unroll
        for (int s = 0; s < S_; s++) acc += Es[e * S_ + s] * W1s[s * H_ + k];
        h1s[e * H_ + k] = fmaxf(acc, 0.0f);
        h2s[e * H_ + k] = 0.0f;
    }

    // h2 pre-activation: stream W2 in 8 chunks of 32 h
    for (int hc = 0; hc < 8; hc++) {
        __syncthreads();  // prior chunk's consumers done / h1 ready on hc==0
#pragma unroll
        for (int l = 0; l < 8; l++) {
            int t = tid + l * 256;       // float4 index 0..2047
            int h = t >> 6;              // 0..31
            int c4 = (t & 63) << 2;      // 0..252
            *reinterpret_cast<float4*>(W2s + h * H_ + c4) =
                *reinterpret_cast<const float4*>(W2 + (size_t)(hc * 32 + h) * H_ + c4);
        }
        __syncthreads();

        for (int c0 = 0; c0 < nslots; c0 += 8) {
            float acc[8];
#pragma unroll
            for (int u = 0; u < 8; u++) acc[u] = h2s[(c0 + u) * H_ + k];
#pragma unroll
            for (int h4 = 0; h4 < 8; h4++) {
                float w0 = W2s[(h4 * 4 + 0) * H_ + k];
                float w1 = W2s[(h4 * 4 + 1) * H_ + k];
                float w2v = W2s[(h4 * 4 + 2) * H_ + k];
                float w3 = W2s[(h4 * 4 + 3) * H_ + k];
#pragma unroll
                for (int u = 0; u < 8; u++) {
                    float4 hv = *reinterpret_cast<const float4*>(
                        h1s + (c0 + u) * H_ + hc * 32 + h4 * 4);
                    acc[u] = fmaf(hv.x, w0, acc[u]);
                    acc[u] = fmaf(hv.y, w1, acc[u]);
                    acc[u] = fmaf(hv.z, w2v, acc[u]);
                    acc[u] = fmaf(hv.w, w3, acc[u]);
                }
            }
#pragma unroll
            for (int u = 0; u < 8; u++) h2s[(c0 + u) * H_ + k] = acc[u];
        }
    }
    __syncthreads();

    // fold into M: M[k][f] = sum_e relu(h2[e][k] + b2[k]) * X[e][f]
    const float b2k = b2[k];
    float Mloc[F_];
#pragma unroll
    for (int f = 0; f < F_; f++) Mloc[f] = 0.0f;

    for (int e = 0; e < nslots; e++) {
        float h2v = fmaxf(h2s[e * H_ + k] + b2k, 0.0f);
#pragma unroll
        for (int f = 0; f < F_; f++) Mloc[f] += h2v * Xs[e * F_ + f];
    }

    float* mrow = g_M + ((size_t)row * (H_ + 1) + k) * F_;
#pragma unroll
    for (int f = 0; f < F_; f += 4) {
        float4 v = make_float4(Mloc[f], Mloc[f + 1], Mloc[f + 2], Mloc[f + 3]);
        *reinterpret_cast<float4*>(mrow + f) = v;
    }

    // ones-row (bias-path aggregation): sum of active X
    if (tid < F_) {
        float s = 0.0f;
        for (int e = 0; e < N_; e++) s += Xs[e * F_ + tid];
        g_M[((size_t)row * (H_ + 1) + H_) * F_ + tid] = s;
    }
}

// ---------------------------------------------------------------------------
// Phase 2: split-K GEMM  P[s][2048][128] partials of  M[2048,4112] @ WkT[4112,128]
// tile: 64 rows x 128 cols x BK=16, 256 threads, 4x8 microtile, 512 CTAs
// ---------------------------------------------------------------------------
__global__ void __launch_bounds__(256) gemm_kernel() {
    __shared__ __align__(16) float As[16][68];   // transposed A tile (+pad)
    __shared__ __align__(16) float Bs[16][128];

    const int tid = threadIdx.x;
    const int tx = tid & 15, ty = tid >> 4;      // tx: 8 cols, ty: 4 rows
    const int r0 = blockIdx.x * 64;
    const int s = blockIdx.y;

    float acc[4][8];
#pragma unroll
    for (int u = 0; u < 4; u++)
#pragma unroll
        for (int v = 0; v < 8; v++) acc[u][v] = 0.0f;

    const int rrL = tid >> 2;            // A-load row 0..63
    const int kkL = (tid & 3) << 2;      // A-load k   0,4,8,12

    for (int ch = s; ch < KAUG / 16 + 1; ch += KSPLIT) {
        const int k0 = ch * 16;
        {
            float4 v = *reinterpret_cast<const float4*>(
                &g_M[(size_t)(r0 + rrL) * KAUG + k0 + kkL]);
            As[kkL + 0][rrL] = v.x;
            As[kkL + 1][rrL] = v.y;
            As[kkL + 2][rrL] = v.z;
            As[kkL + 3][rrL] = v.w;
        }
#pragma unroll
        for (int l = 0; l < 2; l++) {
            int t = tid + l * 256;
            int kk = t >> 5;
            int cc = (t & 31) << 2;
            *reinterpret_cast<float4*>(&Bs[kk][cc]) =
                *reinterpret_cast<const float4*>(&g_WkT[(size_t)(k0 + kk) * C_ + cc]);
        }
        __syncthreads();
#pragma unroll
        for (int kk = 0; kk < 16; kk++) {
            float4 a = *reinterpret_cast<const float4*>(&As[kk][ty * 4]);
            float4 b0 = *reinterpret_cast<const float4*>(&Bs[kk][tx * 8]);
            float4 b1 = *reinterpret_cast<const float4*>(&Bs[kk][tx * 8 + 4]);
            float av[4] = {a.x, a.y, a.z, a.w};
            float bv[8] = {b0.x, b0.y, b0.z, b0.w, b1.x, b1.y, b1.z, b1.w};
#pragma unroll
            for (int u = 0; u < 4; u++)
#pragma unroll
                for (int v = 0; v < 8; v++) acc[u][v] = fmaf(av[u], bv[v], acc[u][v]);
        }
        __syncthreads();
    }

    float* prow = g_P + ((size_t)s * ROWS + r0) * C_;
#pragma unroll
    for (int u = 0; u < 4; u++)
#pragma unroll
        for (int v = 0; v < 8; v += 4) {
            float4 o = make_float4(acc[u][v], acc[u][v + 1], acc[u][v + 2], acc[u][v + 3]);
            *reinterpret_cast<float4*>(&prow[(ty * 4 + u) * C_ + tx * 8 + v]) = o;
        }
}

// ---------------------------------------------------------------------------
// Reduce: Xc[row][c] = relu( sum_s P[s][row][c] + X[row]@Wroot + bconv )
// grid = ROWS (2048) x 128 threads — massively parallel, hides L2 latency
// ---------------------------------------------------------------------------
__global__ void __launch_bounds__(128) reduce_kernel(
    const float* __restrict__ obs,
    const float* __restrict__ Wroot,
    const float* __restrict__ bconv) {
    const int row = blockIdx.x;
    const int c = threadIdx.x;
    const int b = row >> 5, j = row & 31;

    float sum = bconv[c];
#pragma unroll
    for (int s = 0; s < KSPLIT; s++)
        sum += g_P[((size_t)s * ROWS + row) * C_ + c];

    const float* xr = obs + (size_t)b * OBS_STRIDE + j * F_;
#pragma unroll
    for (int f = 0; f < F_; f++) sum += xr[f] * Wroot[f * C_ + c];

    g_Xc[(size_t)row * C_ + c] = fmaxf(sum, 0.0f);
}

// ---------------------------------------------------------------------------
// Phase 3: per batch element — attention softmax pool + dense tanh
// ---------------------------------------------------------------------------
__global__ void __launch_bounds__(256) phase3_kernel(
    const float* __restrict__ attn_w,
    const float* __restrict__ Wd,
    const float* __restrict__ bd,
    float* __restrict__ out) {
    __shared__ __align__(16) float Xc[N_][C_];
    __shared__ float attn[N_];
    __shared__ float logits[N_];
    __shared__ float pooled[C_];

    const int b = blockIdx.x;
    const int tid = threadIdx.x;

    // load Xc tile: 4096 floats = 1024 float4 / 256 threads
#pragma unroll
    for (int l = 0; l < 4; l++) {
        int t = tid + l * 256;
        reinterpret_cast<float4*>(&Xc[0][0])[t] =
            reinterpret_cast<const float4*>(g_Xc + (size_t)b * N_ * C_)[t];
    }
    __syncthreads();

    // attention logits: 8 warps x 4 nodes each
    const int w = tid >> 5, lane = tid & 31;
    const float aw0 = attn_w[lane], aw1 = attn_w[lane + 32];
    const float aw2 = attn_w[lane + 64], aw3 = attn_w[lane + 96];
    for (int j = w * 4; j < w * 4 + 4; j++) {
        float p = Xc[j][lane] * aw0 + Xc[j][lane + 32] * aw1 +
                  Xc[j][lane + 64] * aw2 + Xc[j][lane + 96] * aw3;
#pragma unroll
        for (int off = 16; off; off >>= 1) p += __shfl_xor_sync(0xffffffffu, p, off);
        if (lane == 0) logits[j] = p;
    }
    __syncthreads();

    if (tid < 32) {
        float l = logits[tid];
        float m = l;
#pragma unroll
        for (int off = 16; off; off >>= 1)
            m = fmaxf(m, __shfl_xor_sync(0xffffffffu, m, off));
        float e = expf(l - m);
        float ssum = e;
#pragma unroll
        for (int off = 16; off; off >>= 1) ssum += __shfl_xor_sync(0xffffffffu, ssum, off);
        attn[tid] = e / ssum;
    }
    __syncthreads();

    if (tid < C_) {
        float pc = 0.0f;
#pragma unroll
        for (int j = 0; j < N_; j++) pc += attn[j] * Xc[j][tid];
        pooled[tid] = pc;
    }
    __syncthreads();

    // dense tanh: one output per thread (D_ == 256)
    float sum = bd[tid];
#pragma unroll 8
    for (int cc = 0; cc < C_; cc++) sum += pooled[cc] * Wd[cc * D_ + tid];
    out[(size_t)b * D_ + tid] = tanhf(sum);
}

// ---------------------------------------------------------------------------
extern "C" void kernel_launch(void* const* d_in, const int* in_sizes, int n_in,
                              void* d_out, int out_size) {
    const float* obs    = (const float*)d_in[0];
    const float* W1     = (const float*)d_in[1];
    const float* b1     = (const float*)d_in[2];
    const float* W2     = (const float*)d_in[3];
    const float* b2     = (const float*)d_in[4];
    const float* Wk     = (const float*)d_in[5];
    const float* bk     = (const float*)d_in[6];
    const float* Wroot  = (const float*)d_in[7];
    const float* bconv  = (const float*)d_in[8];
    const float* attn_w = (const float*)d_in[9];
    const float* Wd     = (const float*)d_in[10];
    const float* bd     = (const float*)d_in[11];
    float* out = (float*)d_out;

    cudaFuncSetAttribute(phase1_kernel,
                         cudaFuncAttributeMaxDynamicSharedMemorySize,
                         P1_SMEM_BYTES);

    prep_kernel<<<(KAUG * C_ + 255) / 256, 256>>>(Wk, bk);
    phase1_kernel<<<ROWS, 256, P1_SMEM_BYTES>>>(obs, W1, b1, W2, b2);
    gemm_kernel<<<dim3(ROWS / 64, KSPLIT), 256>>>();
    reduce_kernel<<<ROWS, 128>>>(obs, Wroot, bconv);
    phase3_kernel<<<B_, 256>>>(attn_w, Wd, bd, out);
}

// round 4
// speedup vs baseline: 1.5775x; 1.1963x over previous
#include <cuda_runtime.h>

// dims
#define B_ 64
#define N_ 32
#define F_ 16
#define S_ 8
#define C_ 128
#define H_ 256
#define D_ 256
#define OBS_STRIDE 9728
#define A_OFF 512        // N_*F_
#define E_OFF 1536       // N_*F_ + N_*N_
#define KAUG 4112        // (H_+1)*F_
#define KCHUNKS 257      // KAUG/16, exact
#define ROWS 2048        // B_*N_
#define KSPLIT 16

typedef unsigned long long ull;

// packed fp32x2 FMA (Blackwell FFMA2): d = a*b + c elementwise on 2 lanes
#define FMA2(d, a, b, c) \
    asm("fma.rn.f32x2 %0, %1, %2, %3;" : "=l"(d) : "l"(a), "l"(b), "l"(c))
#define PACK2(d, lo, hi)                                 \
    asm("mov.b64 %0, {%1, %2};"                          \
        : "=l"(d)                                        \
        : "r"(__float_as_uint(lo)), "r"(__float_as_uint(hi)))
#define UNPACK2(lo, hi, s) \
    asm("mov.b64 {%0, %1}, %2;" : "=r"(lo), "=r"(hi) : "l"(s))

// scratch (static device allocations; no runtime alloc)
__device__ __align__(16) float g_WkT[KAUG * C_];      // augmented Wk  [k=(h,f)][c]
__device__ __align__(16) float g_M[ROWS * KAUG];      // M[b*N+j][h*16+f]
__device__ __align__(16) float g_P[KSPLIT * ROWS * C_];
__device__ __align__(16) float g_Xc[ROWS * C_];       // post-conv node features

// ---------------------------------------------------------------------------
// Prep: build augmented WkT (Wk rows + bk row) in [k][c] layout
// ---------------------------------------------------------------------------
__global__ void prep_kernel(const float* __restrict__ Wk,
                            const float* __restrict__ bk) {
    int t = blockIdx.x * blockDim.x + threadIdx.x;
    if (t < KAUG * C_) {
        int k = t >> 7, c = t & 127;
        int h = k >> 4, f = k & 15;
        g_WkT[t] = (h < H_) ? Wk[h * (C_ * F_) + c * F_ + f] : bk[c * F_ + f];
    }
}

// ---------------------------------------------------------------------------
// Phase 1: per (b,j) row — compact active edges, edge MLP (FFMA2), accumulate
//   M[k][f] = sum_e relu(h2[e][k]+b2[k]) * X[e][f];  M[256][f] = sum_e X[e][f]
// h1 stored transposed h1T[h][e] (stride 36) so edge pairs load as ulonglong2
// directly into packed f32x2 operands. W2 read via coalesced __ldg (k = lane).
// ---------------------------------------------------------------------------
#define H1T_STRIDE 36

// NP = number of edge pairs to process (8 -> 16 slots, 16 -> 32 slots)
template <int NP>
__device__ __forceinline__ void h2_fold(const float* __restrict__ h1T,
                                        const float* __restrict__ Xs,
                                        const float* __restrict__ W2,
                                        float b2k, int k, float* Mout) {
    ull acc2[NP];
#pragma unroll
    for (int p = 0; p < NP; p++) acc2[p] = 0ull;

    const float* w2col = W2 + k;
#pragma unroll 2
    for (int h = 0; h < H_; h++) {
        float w = __ldg(&w2col[h * H_]);
        ull ww;
        PACK2(ww, w, w);
        const ulonglong2* hp =
            reinterpret_cast<const ulonglong2*>(h1T + h * H1T_STRIDE);
#pragma unroll
        for (int q = 0; q < NP / 2; q++) {
            ulonglong2 pv = hp[q];
            FMA2(acc2[2 * q + 0], pv.x, ww, acc2[2 * q + 0]);
            FMA2(acc2[2 * q + 1], pv.y, ww, acc2[2 * q + 1]);
        }
    }

    // fold: M[f] += relu(h2[e]+b2) * X[e][f], FFMA2 along f
    ull Ml[8];
#pragma unroll
    for (int q = 0; q < 8; q++) Ml[q] = 0ull;

#pragma unroll
    for (int p = 0; p < NP; p++) {
        unsigned u0, u1;
        UNPACK2(u0, u1, acc2[p]);
        float f0 = fmaxf(__uint_as_float(u0) + b2k, 0.0f);
        float f1 = fmaxf(__uint_as_float(u1) + b2k, 0.0f);
        ull hh0, hh1;
        PACK2(hh0, f0, f0);
        PACK2(hh1, f1, f1);
        const ulonglong2* x0 =
            reinterpret_cast<const ulonglong2*>(Xs + (2 * p) * F_);
        const ulonglong2* x1 =
            reinterpret_cast<const ulonglong2*>(Xs + (2 * p + 1) * F_);
        ulonglong2 xa = x0[0], xb = x0[1];
        FMA2(Ml[0], xa.x, hh0, Ml[0]);
        FMA2(Ml[1], xa.y, hh0, Ml[1]);
        FMA2(Ml[2], xb.x, hh0, Ml[2]);
        FMA2(Ml[3], xb.y, hh0, Ml[3]);
        ulonglong2 xc = x1[0], xd = x1[1];
        FMA2(Ml[4], xc.x, hh1, Ml[4]);
        FMA2(Ml[5], xc.y, hh1, Ml[5]);
        FMA2(Ml[6], xd.x, hh1, Ml[6]);
        FMA2(Ml[7], xd.y, hh1, Ml[7]);
    }
    // Ml[0..3] = edge-even contributions f0..15, Ml[4..7] = edge-odd f0..15
#pragma unroll
    for (int q = 0; q < 4; q++) {
        unsigned a0, a1, b0v, b1v;
        UNPACK2(a0, a1, Ml[q]);
        UNPACK2(b0v, b1v, Ml[q + 4]);
        Mout[4 * q + 0] = __uint_as_float(a0) + 0.0f;
        Mout[4 * q + 1] = __uint_as_float(a1);
        Mout[4 * q + 2] = 0.0f;  // placeholder, fixed below
        Mout[4 * q + 3] = 0.0f;
        // recombine: even-edge and odd-edge partial sums share same f index
        Mout[4 * q + 0] = __uint_as_float(a0) + __uint_as_float(b0v);
        Mout[4 * q + 1] = __uint_as_float(a1) + __uint_as_float(b1v);
    }
    // note: Ml[q] covers f = 4q..4q+1? No — xa.x is (f0,f1), xa.y is (f2,f3),
    // xb.x (f4,f5), xb.y (f6,f7)... Ml[0]=(f0,f1), Ml[1]=(f2,f3), Ml[2]=(f4,f5),
    // Ml[3]=(f6,f7) — but that's only f0..7! Fix: use 2 ulonglong2 per edge
    // (16 floats). Corrected below in caller-visible version.
}

__global__ void __launch_bounds__(256) phase1_kernel(
    const float* __restrict__ obs,
    const float* __restrict__ W1,
    const float* __restrict__ b1,
    const float* __restrict__ W2,
    const float* __restrict__ b2) {
    __shared__ __align__(16) float h1T[H_ * H1T_STRIDE];  // [h][e], 36.9KB
    __shared__ __align__(16) float Xs[N_ * F_];
    __shared__ float Es[N_ * S_];
    __shared__ int actIdx[N_];
    __shared__ int s_nact;

    const int tid = threadIdx.x;
    const int row = blockIdx.x;
    const int b = row >> 5, j = row & 31;
    const float* orow = obs + (size_t)b * OBS_STRIDE;

    // deterministic compaction of active columns (warp 0)
    if (tid < 32) {
        float a = orow[A_OFF + j * N_ + tid];
        unsigned m = __ballot_sync(0xffffffffu, a != 0.0f);
        int pos = __popc(m & ((1u << tid) - 1u));
        if (a != 0.0f) actIdx[pos] = tid;
        if (tid == 0) s_nact = __popc(m);
    }
    __syncthreads();

    const int nact = s_nact;
    const int ns = (nact <= 16) ? 16 : 32;

    // gather X and E for active slots; zero padding (X=0 kills padded slots)
    for (int t = tid; t < N_ * F_; t += 256) {
        int e = t >> 4, f = t & 15;
        Xs[e * F_ + f] = (e < nact) ? orow[actIdx[e] * F_ + f] : 0.0f;
    }
    for (int t = tid; t < N_ * S_; t += 256) {
        int e = t >> 3, s = t & 7;
        Es[e * S_ + s] = (e < nact) ? orow[E_OFF + (j * N_ + actIdx[e]) * S_ + s] : 0.0f;
    }
    __syncthreads();

    const int k = tid;  // unit index (H_ == 256 == blockDim)

    // h1 = relu(E @ W1 + b1), stored transposed [h][e]
    float w1r[S_];
#pragma unroll
    for (int s = 0; s < S_; s++) w1r[s] = __ldg(&W1[s * H_ + k]);
    const float b1k = __ldg(&b1[k]);
    for (int e = 0; e < ns; e++) {
        float acc = b1k;
#pragma unroll
        for (int s = 0; s < S_; s++) acc += Es[e * S_ + s] * w1r[s];
        h1T[k * H1T_STRIDE + e] = fmaxf(acc, 0.0f);
    }
    __syncthreads();

    const float b2k = __ldg(&b2[k]);
    float Mloc[F_];

    // h2 via packed FFMA2; accumulators in registers across all 256 h
    if (ns == 16) {
        ull acc2[8];
#pragma unroll
        for (int p = 0; p < 8; p++) acc2[p] = 0ull;
        const float* w2col = W2 + k;
#pragma unroll 2
        for (int h = 0; h < H_; h++) {
            float w = __ldg(&w2col[h * H_]);
            ull ww;
            PACK2(ww, w, w);
            const ulonglong2* hp =
                reinterpret_cast<const ulonglong2*>(h1T + h * H1T_STRIDE);
#pragma unroll
            for (int q = 0; q < 4; q++) {
                ulonglong2 pv = hp[q];
                FMA2(acc2[2 * q + 0], pv.x, ww, acc2[2 * q + 0]);
                FMA2(acc2[2 * q + 1], pv.y, ww, acc2[2 * q + 1]);
            }
        }
        // fold 16 edges
        ull Ml[8];
#pragma unroll
        for (int q = 0; q < 8; q++) Ml[q] = 0ull;
#pragma unroll
        for (int p = 0; p < 8; p++) {
            unsigned u0, u1;
            UNPACK2(u0, u1, acc2[p]);
            float f0 = fmaxf(__uint_as_float(u0) + b2k, 0.0f);
            float f1 = fmaxf(__uint_as_float(u1) + b2k, 0.0f);
            ull hh0, hh1;
            PACK2(hh0, f0, f0);
            PACK2(hh1, f1, f1);
            const ulonglong2* x0 =
                reinterpret_cast<const ulonglong2*>(Xs + (2 * p) * F_);
            const ulonglong2* x1 =
                reinterpret_cast<const ulonglong2*>(Xs + (2 * p + 1) * F_);
            ulonglong2 xa = x0[0], xb = x0[1];
            FMA2(Ml[0], xa.x, hh0, Ml[0]);
            FMA2(Ml[1], xa.y, hh0, Ml[1]);
            FMA2(Ml[2], xb.x, hh0, Ml[2]);
            FMA2(Ml[3], xb.y, hh0, Ml[3]);
            ulonglong2 xc = x1[0], xd = x1[1];
            FMA2(Ml[4], xc.x, hh1, Ml[4]);
            FMA2(Ml[5], xc.y, hh1, Ml[5]);
            FMA2(Ml[6], xd.x, hh1, Ml[6]);
            FMA2(Ml[7], xd.y, hh1, Ml[7]);
        }
#pragma unroll
        for (int q = 0; q < 4; q++) {
            unsigned a0, a1, c0v, c1v;
            UNPACK2(a0, a1, Ml[q]);       // even edges, f = 4q..4q+1? see map
            UNPACK2(c0v, c1v, Ml[q + 4]); // odd edges, same f pair
            Mloc[4 * q + 0] = 0.0f;       // overwritten below
            Mloc[4 * q + 1] = 0.0f;
            Mloc[4 * q + 2] = 0.0f;
            Mloc[4 * q + 3] = 0.0f;
            // Ml[q] holds f-pair (2q, 2q+1) wait — correct mapping:
            // xa.x=(f0,f1) xa.y=(f2,f3) xb.x=(f4,f5) xb.y=(f6,f7)
            // -> Ml[0..3] = f(0,1),(2,3),(4,5),(6,7) for even edges... but F_=16!
        }
        // F_=16 needs 4 ulonglong2 per edge; redo fold correctly:
        {
#pragma unroll
            for (int f = 0; f < F_; f++) Mloc[f] = 0.0f;
#pragma unroll
            for (int p = 0; p < 8; p++) {
                unsigned u0, u1;
                UNPACK2(u0, u1, acc2[p]);
                float f0 = fmaxf(__uint_as_float(u0) + b2k, 0.0f);
                float f1 = fmaxf(__uint_as_float(u1) + b2k, 0.0f);
#pragma unroll
                for (int f = 0; f < F_; f++) {
                    Mloc[f] += f0 * Xs[(2 * p) * F_ + f];
                    Mloc[f] += f1 * Xs[(2 * p + 1) * F_ + f];
                }
            }
        }
    } else {
        ull acc2[16];
#pragma unroll
        for (int p = 0; p < 16; p++) acc2[p] = 0ull;
        const float* w2col = W2 + k;
        for (int h = 0; h < H_; h++) {
            float w = __ldg(&w2col[h * H_]);
            ull ww;
            PACK2(ww, w, w);
            const ulonglong2* hp =
                reinterpret_cast<const ulonglong2*>(h1T + h * H1T_STRIDE);
#pragma unroll
            for (int q = 0; q < 8; q++) {
                ulonglong2 pv = hp[q];
                FMA2(acc2[2 * q + 0], pv.x, ww, acc2[2 * q + 0]);
                FMA2(acc2[2 * q + 1], pv.y, ww, acc2[2 * q + 1]);
            }
        }
#pragma unroll
        for (int f = 0; f < F_; f++) Mloc[f] = 0.0f;
#pragma unroll
        for (int p = 0; p < 16; p++) {
            unsigned u0, u1;
            UNPACK2(u0, u1, acc2[p]);
            float f0 = fmaxf(__uint_as_float(u0) + b2k, 0.0f);
            float f1 = fmaxf(__uint_as_float(u1) + b2k, 0.0f);
#pragma unroll
            for (int f = 0; f < F_; f++) {
                Mloc[f] += f0 * Xs[(2 * p) * F_ + f];
                Mloc[f] += f1 * Xs[(2 * p + 1) * F_ + f];
            }
        }
    }

    float* mrow = g_M + ((size_t)row * (H_ + 1) + k) * F_;
#pragma unroll
    for (int f = 0; f < F_; f += 4) {
        float4 v = make_float4(Mloc[f], Mloc[f + 1], Mloc[f + 2], Mloc[f + 3]);
        *reinterpret_cast<float4*>(mrow + f) = v;
    }

    // ones-row (bias-path aggregation): sum of active X
    if (tid < F_) {
        float s = 0.0f;
        for (int e = 0; e < N_; e++) s += Xs[e * F_ + tid];
        g_M[((size_t)row * (H_ + 1) + H_) * F_ + tid] = s;
    }
}

// ---------------------------------------------------------------------------
// Phase 2: split-K GEMM with FFMA2.  P[s][2048][128] partials of
// M[2048,4112] @ WkT[4112,128].  64x128x16 tile, 256 thr, 4x8 microtile
// (2 row-pairs x 8 cols packed).
// ---------------------------------------------------------------------------
__global__ void __launch_bounds__(256) gemm_kernel() {
    __shared__ __align__(16) float As[16][68];   // transposed A tile (+pad)
    __shared__ __align__(16) float Bs[16][128];

    const int tid = threadIdx.x;
    const int tx = tid & 15, ty = tid >> 4;      // tx: 8 cols, ty: 4 rows
    const int r0 = blockIdx.x * 64;
    const int s = blockIdx.y;

    ull acc2[2][8];
#pragma unroll
    for (int p = 0; p < 2; p++)
#pragma unroll
        for (int v = 0; v < 8; v++) acc2[p][v] = 0ull;

    const int rrL = tid >> 2;            // A-load row 0..63
    const int kkL = (tid & 3) << 2;      // A-load k   0,4,8,12

    for (int ch = s; ch < KCHUNKS; ch += KSPLIT) {
        const int k0 = ch * 16;
        {
            float4 v = *reinterpret_cast<const float4*>(
                &g_M[(size_t)(r0 + rrL) * KAUG + k0 + kkL]);
            As[kkL + 0][rrL] = v.x;
            As[kkL + 1][rrL] = v.y;
            As[kkL + 2][rrL] = v.z;
            As[kkL + 3][rrL] = v.w;
        }
#pragma unroll
        for (int l = 0; l < 2; l++) {
            int t = tid + l * 256;
            int kk = t >> 5;
            int cc = (t & 31) << 2;
            *reinterpret_cast<float4*>(&Bs[kk][cc]) =
                *reinterpret_cast<const float4*>(&g_WkT[(size_t)(k0 + kk) * C_ + cc]);
        }
        __syncthreads();
#pragma unroll
        for (int kk = 0; kk < 16; kk++) {
            ulonglong2 a = *reinterpret_cast<const ulonglong2*>(&As[kk][ty * 4]);
            float4 b0 = *reinterpret_cast<const float4*>(&Bs[kk][tx * 8]);
            float4 b1 = *reinterpret_cast<const float4*>(&Bs[kk][tx * 8 + 4]);
            ull bb[8];
            PACK2(bb[0], b0.x, b0.x);
            PACK2(bb[1], b0.y, b0.y);
            PACK2(bb[2], b0.z, b0.z);
            PACK2(bb[3], b0.w, b0.w);
            PACK2(bb[4], b1.x, b1.x);
            PACK2(bb[5], b1.y, b1.y);
            PACK2(bb[6], b1.z, b1.z);
            PACK2(bb[7], b1.w, b1.w);
#pragma unroll
            for (int v = 0; v < 8; v++) {
                FMA2(acc2[0][v], a.x, bb[v], acc2[0][v]);
                FMA2(acc2[1][v], a.y, bb[v], acc2[1][v]);
            }
        }
        __syncthreads();
    }

    float* prow = g_P + ((size_t)s * ROWS + r0) * C_;
#pragma unroll
    for (int p = 0; p < 2; p++) {
        unsigned lo[8], hi[8];
#pragma unroll
        for (int v = 0; v < 8; v++) UNPACK2(lo[v], hi[v], acc2[p][v]);
        const int ra = ty * 4 + 2 * p;
#pragma unroll
        for (int half = 0; half < 2; half++) {
            float4 o0 = make_float4(
                __uint_as_float(half ? hi[0] : lo[0]),
                __uint_as_float(half ? hi[1] : lo[1]),
                __uint_as_float(half ? hi[2] : lo[2]),
                __uint_as_float(half ? hi[3] : lo[3]));
            float4 o1 = make_float4(
                __uint_as_float(half ? hi[4] : lo[4]),
                __uint_as_float(half ? hi[5] : lo[5]),
                __uint_as_float(half ? hi[6] : lo[6]),
                __uint_as_float(half ? hi[7] : lo[7]));
            *reinterpret_cast<float4*>(&prow[(ra + half) * C_ + tx * 8]) = o0;
            *reinterpret_cast<float4*>(&prow[(ra + half) * C_ + tx * 8 + 4]) = o1;
        }
    }
}

// ---------------------------------------------------------------------------
// Reduce: Xc[row][c] = relu( sum_s P[s][row][c] + X[row]@Wroot + bconv )
// ---------------------------------------------------------------------------
__global__ void __launch_bounds__(128) reduce_kernel(
    const float* __restrict__ obs,
    const float* __restrict__ Wroot,
    const float* __restrict__ bconv) {
    const int row = blockIdx.x;
    const int c = threadIdx.x;
    const int b = row >> 5, j = row & 31;

    float sum = bconv[c];
#pragma unroll
    for (int s = 0; s < KSPLIT; s++)
        sum += g_P[((size_t)s * ROWS + row) * C_ + c];

    const float* xr = obs + (size_t)b * OBS_STRIDE + j * F_;
#pragma unroll
    for (int f = 0; f < F_; f++) sum += xr[f] * Wroot[f * C_ + c];

    g_Xc[(size_t)row * C_ + c] = fmaxf(sum, 0.0f);
}

// ---------------------------------------------------------------------------
// Phase 3: per batch element — attention softmax pool + dense tanh
// ---------------------------------------------------------------------------
__global__ void __launch_bounds__(256) phase3_kernel(
    const float* __restrict__ attn_w,
    const float* __restrict__ Wd,
    const float* __restrict__ bd,
    float* __restrict__ out) {
    __shared__ __align__(16) float Xc[N_][C_];
    __shared__ float attn[N_];
    __shared__ float logits[N_];
    __shared__ float pooled[C_];

    const int b = blockIdx.x;
    const int tid = threadIdx.x;

#pragma unroll
    for (int l = 0; l < 4; l++) {
        int t = tid + l * 256;
        reinterpret_cast<float4*>(&Xc[0][0])[t] =
            reinterpret_cast<const float4*>(g_Xc + (size_t)b * N_ * C_)[t];
    }
    __syncthreads();

    const int w = tid >> 5, lane = tid & 31;
    const float aw0 = attn_w[lane], aw1 = attn_w[lane + 32];
    const float aw2 = attn_w[lane + 64], aw3 = attn_w[lane + 96];
    for (int j = w * 4; j < w * 4 + 4; j++) {
        float p = Xc[j][lane] * aw0 + Xc[j][lane + 32] * aw1 +
                  Xc[j][lane + 64] * aw2 + Xc[j][lane + 96] * aw3;
#pragma unroll
        for (int off = 16; off; off >>= 1) p += __shfl_xor_sync(0xffffffffu, p, off);
        if (lane == 0) logits[j] = p;
    }
    __syncthreads();

    if (tid < 32) {
        float l = logits[tid];
        float m = l;
#pragma unroll
        for (int off = 16; off; off >>= 1)
            m = fmaxf(m, __shfl_xor_sync(0xffffffffu, m, off));
        float e = expf(l - m);
        float ssum = e;
#pragma unroll
        for (int off = 16; off; off >>= 1) ssum += __shfl_xor_sync(0xffffffffu, ssum, off);
        attn[tid] = e / ssum;
    }
    __syncthreads();

    if (tid < C_) {
        float pc = 0.0f;
#pragma unroll
        for (int j = 0; j < N_; j++) pc += attn[j] * Xc[j][tid];
        pooled[tid] = pc;
    }
    __syncthreads();

    float sum = bd[tid];
#pragma unroll 8
    for (int cc = 0; cc < C_; cc++) sum += pooled[cc] * Wd[cc * D_ + tid];
    out[(size_t)b * D_ + tid] = tanhf(sum);
}

// ---------------------------------------------------------------------------
extern "C" void kernel_launch(void* const* d_in, const int* in_sizes, int n_in,
                              void* d_out, int out_size) {
    const float* obs    = (const float*)d_in[0];
    const float* W1     = (const float*)d_in[1];
    const float* b1     = (const float*)d_in[2];
    const float* W2     = (const float*)d_in[3];
    const float* b2     = (const float*)d_in[4];
    const float* Wk     = (const float*)d_in[5];
    const float* bk     = (const float*)d_in[6];
    const float* Wroot  = (const float*)d_in[7];
    const float* bconv  = (const float*)d_in[8];
    const float* attn_w = (const float*)d_in[9];
    const float* Wd     = (const float*)d_in[10];
    const float* bd     = (const float*)d_in[11];
    float* out = (float*)d_out;

    prep_kernel<<<(KAUG * C_ + 255) / 256, 256>>>(Wk, bk);
    phase1_kernel<<<ROWS, 256>>>(obs, W1, b1, W2, b2);
    gemm_kernel<<<dim3(ROWS / 64, KSPLIT), 256>>>();
    reduce_kernel<<<ROWS, 128>>>(obs, Wroot, bconv);
    phase3_kernel<<<B_, 256>>>(attn_w, Wd, bd, out);
}

// round 5
// speedup vs baseline: 1.6162x; 1.0245x over previous
#include <cuda_runtime.h>

// dims
#define B_ 64
#define N_ 32
#define F_ 16
#define S_ 8
#define C_ 128
#define H_ 256
#define D_ 256
#define OBS_STRIDE 9728
#define A_OFF 512        // N_*F_
#define E_OFF 1536       // N_*F_ + N_*N_
#define KAUG 4112        // (H_+1)*F_
#define KCHUNKS 257      // KAUG/16, exact
#define ROWS 2048        // B_*N_
#define KSPLIT 16

typedef unsigned long long ull;

// packed fp32x2 FMA (Blackwell FFMA2): d = a*b + c elementwise on 2 lanes
#define FMA2(d, a, b, c) \
    asm("fma.rn.f32x2 %0, %1, %2, %3;" : "=l"(d) : "l"(a), "l"(b), "l"(c))
#define PACK2(d, lo, hi)                                 \
    asm("mov.b64 %0, {%1, %2};"                          \
        : "=l"(d)                                        \
        : "r"(__float_as_uint(lo)), "r"(__float_as_uint(hi)))
#define UNPACK2(lo, hi, s) \
    asm("mov.b64 {%0, %1}, %2;" : "=r"(lo), "=r"(hi) : "l"(s))

// scratch (static device allocations; no runtime alloc)
__device__ __align__(16) float g_WkT[KAUG * C_];      // augmented Wk  [k=(h,f)][c]
__device__ __align__(16) float g_M[ROWS * KAUG];      // M[b*N+j][h*16+f]
__device__ __align__(16) float g_P[KSPLIT * ROWS * C_];
__device__ __align__(16) float g_Xc[ROWS * C_];       // post-conv node features

// ---------------------------------------------------------------------------
// Prep: build augmented WkT (Wk rows + bk row) in [k][c] layout
// ---------------------------------------------------------------------------
__global__ void prep_kernel(const float* __restrict__ Wk,
                            const float* __restrict__ bk) {
    int t = blockIdx.x * blockDim.x + threadIdx.x;
    if (t < KAUG * C_) {
        int k = t >> 7, c = t & 127;
        int h = k >> 4, f = k & 15;
        g_WkT[t] = (h < H_) ? Wk[h * (C_ * F_) + c * F_ + f] : bk[c * F_ + f];
    }
}

// ---------------------------------------------------------------------------
// Phase 1: per (b,j) row — compact active edges, edge MLP (FFMA2), accumulate
//   M[k][f] = sum_e relu(h2[e][k]+b2[k]) * X[e][f];  M[256][f] = sum_e X[e][f]
// h1 stored transposed h1T[h][e] (stride 36) so edge pairs load as ulonglong2
// directly into packed f32x2 operands. W2 column streamed with an 8-deep
// front-batched LDG prefetch (MLP=8) so L2 latency is overlapped.
// ---------------------------------------------------------------------------
#define H1T_STRIDE 36

__global__ void __launch_bounds__(256) phase1_kernel(
    const float* __restrict__ obs,
    const float* __restrict__ W1,
    const float* __restrict__ b1,
    const float* __restrict__ W2,
    const float* __restrict__ b2) {
    __shared__ __align__(16) float h1T[H_ * H1T_STRIDE];  // [h][e], 36.9KB
    __shared__ __align__(16) float Xs[N_ * F_];
    __shared__ float Es[N_ * S_];
    __shared__ int actIdx[N_];
    __shared__ int s_nact;

    const int tid = threadIdx.x;
    const int row = blockIdx.x;
    const int b = row >> 5, j = row & 31;
    const float* orow = obs + (size_t)b * OBS_STRIDE;

    // deterministic compaction of active columns (warp 0)
    if (tid < 32) {
        float a = orow[A_OFF + j * N_ + tid];
        unsigned m = __ballot_sync(0xffffffffu, a != 0.0f);
        int pos = __popc(m & ((1u << tid) - 1u));
        if (a != 0.0f) actIdx[pos] = tid;
        if (tid == 0) s_nact = __popc(m);
    }
    __syncthreads();

    const int nact = s_nact;
    const int ns = (nact <= 16) ? 16 : 32;

    // gather X and E for active slots; zero padding (X=0 kills padded slots)
    for (int t = tid; t < N_ * F_; t += 256) {
        int e = t >> 4, f = t & 15;
        Xs[e * F_ + f] = (e < nact) ? orow[actIdx[e] * F_ + f] : 0.0f;
    }
    for (int t = tid; t < N_ * S_; t += 256) {
        int e = t >> 3, s = t & 7;
        Es[e * S_ + s] = (e < nact) ? orow[E_OFF + (j * N_ + actIdx[e]) * S_ + s] : 0.0f;
    }
    __syncthreads();

    const int k = tid;  // unit index (H_ == 256 == blockDim)

    // h1 = relu(E @ W1 + b1), stored transposed [h][e]
    float w1r[S_];
#pragma unroll
    for (int s = 0; s < S_; s++) w1r[s] = __ldg(&W1[s * H_ + k]);
    const float b1k = __ldg(&b1[k]);
    for (int e = 0; e < ns; e++) {
        float acc = b1k;
#pragma unroll
        for (int s = 0; s < S_; s++) acc += Es[e * S_ + s] * w1r[s];
        h1T[k * H1T_STRIDE + e] = fmaxf(acc, 0.0f);
    }
    __syncthreads();

    const float b2k = __ldg(&b2[k]);
    const float* w2col = W2 + k;
    float Mloc[F_];

    if (ns == 16) {
        ull acc2[8];
#pragma unroll
        for (int p = 0; p < 8; p++) acc2[p] = 0ull;

        for (int h0 = 0; h0 < H_; h0 += 8) {
            // front-batched prefetch: 8 independent LDGs in flight
            float w[8];
#pragma unroll
            for (int i = 0; i < 8; i++) w[i] = __ldg(&w2col[(h0 + i) * H_]);
#pragma unroll
            for (int i = 0; i < 8; i++) {
                ull ww;
                PACK2(ww, w[i], w[i]);
                const ulonglong2* hp = reinterpret_cast<const ulonglong2*>(
                    h1T + (h0 + i) * H1T_STRIDE);
#pragma unroll
                for (int q = 0; q < 4; q++) {
                    ulonglong2 pv = hp[q];
                    FMA2(acc2[2 * q + 0], pv.x, ww, acc2[2 * q + 0]);
                    FMA2(acc2[2 * q + 1], pv.y, ww, acc2[2 * q + 1]);
                }
            }
        }

#pragma unroll
        for (int f = 0; f < F_; f++) Mloc[f] = 0.0f;
#pragma unroll
        for (int p = 0; p < 8; p++) {
            unsigned u0, u1;
            UNPACK2(u0, u1, acc2[p]);
            float f0 = fmaxf(__uint_as_float(u0) + b2k, 0.0f);
            float f1 = fmaxf(__uint_as_float(u1) + b2k, 0.0f);
#pragma unroll
            for (int f = 0; f < F_; f++) {
                Mloc[f] += f0 * Xs[(2 * p) * F_ + f];
                Mloc[f] += f1 * Xs[(2 * p + 1) * F_ + f];
            }
        }
    } else {
        ull acc2[16];
#pragma unroll
        for (int p = 0; p < 16; p++) acc2[p] = 0ull;

        for (int h0 = 0; h0 < H_; h0 += 4) {
            float w[4];
#pragma unroll
            for (int i = 0; i < 4; i++) w[i] = __ldg(&w2col[(h0 + i) * H_]);
#pragma unroll
            for (int i = 0; i < 4; i++) {
                ull ww;
                PACK2(ww, w[i], w[i]);
                const ulonglong2* hp = reinterpret_cast<const ulonglong2*>(
                    h1T + (h0 + i) * H1T_STRIDE);
#pragma unroll
                for (int q = 0; q < 8; q++) {
                    ulonglong2 pv = hp[q];
                    FMA2(acc2[2 * q + 0], pv.x, ww, acc2[2 * q + 0]);
                    FMA2(acc2[2 * q + 1], pv.y, ww, acc2[2 * q + 1]);
                }
            }
        }

#pragma unroll
        for (int f = 0; f < F_; f++) Mloc[f] = 0.0f;
#pragma unroll
        for (int p = 0; p < 16; p++) {
            unsigned u0, u1;
            UNPACK2(u0, u1, acc2[p]);
            float f0 = fmaxf(__uint_as_float(u0) + b2k, 0.0f);
            float f1 = fmaxf(__uint_as_float(u1) + b2k, 0.0f);
#pragma unroll
            for (int f = 0; f < F_; f++) {
                Mloc[f] += f0 * Xs[(2 * p) * F_ + f];
                Mloc[f] += f1 * Xs[(2 * p + 1) * F_ + f];
            }
        }
    }

    float* mrow = g_M + ((size_t)row * (H_ + 1) + k) * F_;
#pragma unroll
    for (int f = 0; f < F_; f += 4) {
        float4 v = make_float4(Mloc[f], Mloc[f + 1], Mloc[f + 2], Mloc[f + 3]);
        *reinterpret_cast<float4*>(mrow + f) = v;
    }

    // ones-row (bias-path aggregation): sum of active X
    if (tid < F_) {
        float s = 0.0f;
        for (int e = 0; e < N_; e++) s += Xs[e * F_ + tid];
        g_M[((size_t)row * (H_ + 1) + H_) * F_ + tid] = s;
    }
}

// ---------------------------------------------------------------------------
// Phase 2: split-K GEMM with FFMA2 + register double-buffering.
// P[s][2048][128] partials of M[2048,4112] @ WkT[4112,128].
// 64x128x16 tile, 256 thr, (2 row-pairs) x 8 cols microtile.
// ---------------------------------------------------------------------------
__global__ void __launch_bounds__(256) gemm_kernel() {
    __shared__ __align__(16) float As[16][68];   // transposed A tile (+pad)
    __shared__ __align__(16) float Bs[16][128];

    const int tid = threadIdx.x;
    const int tx = tid & 15, ty = tid >> 4;      // tx: 8 cols, ty: 4 rows
    const int r0 = blockIdx.x * 64;
    const int s = blockIdx.y;

    ull acc2[2][8];
#pragma unroll
    for (int p = 0; p < 2; p++)
#pragma unroll
        for (int v = 0; v < 8; v++) acc2[p][v] = 0ull;

    const int rrL = tid >> 2;            // A-load row 0..63
    const int kkL = (tid & 3) << 2;      // A-load k   0,4,8,12
    const int kkB = tid >> 5;            // B-load base k 0..7
    const int ccB = (tid & 31) << 2;     // B-load col

    // prefetch first chunk
    int ch = s;
    float4 aP = *reinterpret_cast<const float4*>(
        &g_M[(size_t)(r0 + rrL) * KAUG + ch * 16 + kkL]);
    float4 bP0 = *reinterpret_cast<const float4*>(
        &g_WkT[(size_t)(ch * 16 + kkB) * C_ + ccB]);
    float4 bP1 = *reinterpret_cast<const float4*>(
        &g_WkT[(size_t)(ch * 16 + kkB + 8) * C_ + ccB]);

    while (true) {
        // commit prefetched fragments to smem
        As[kkL + 0][rrL] = aP.x;
        As[kkL + 1][rrL] = aP.y;
        As[kkL + 2][rrL] = aP.z;
        As[kkL + 3][rrL] = aP.w;
        *reinterpret_cast<float4*>(&Bs[kkB][ccB]) = bP0;
        *reinterpret_cast<float4*>(&Bs[kkB + 8][ccB]) = bP1;
        __syncthreads();

        // prefetch next chunk (overlaps with FMA block below)
        const int chn = ch + KSPLIT;
        const bool more = (chn < KCHUNKS);
        if (more) {
            aP = *reinterpret_cast<const float4*>(
                &g_M[(size_t)(r0 + rrL) * KAUG + chn * 16 + kkL]);
            bP0 = *reinterpret_cast<const float4*>(
                &g_WkT[(size_t)(chn * 16 + kkB) * C_ + ccB]);
            bP1 = *reinterpret_cast<const float4*>(
                &g_WkT[(size_t)(chn * 16 + kkB + 8) * C_ + ccB]);
        }

#pragma unroll
        for (int kk = 0; kk < 16; kk++) {
            ulonglong2 a = *reinterpret_cast<const ulonglong2*>(&As[kk][ty * 4]);
            float4 b0 = *reinterpret_cast<const float4*>(&Bs[kk][tx * 8]);
            float4 b1 = *reinterpret_cast<const float4*>(&Bs[kk][tx * 8 + 4]);
            ull bb[8];
            PACK2(bb[0], b0.x, b0.x);
            PACK2(bb[1], b0.y, b0.y);
            PACK2(bb[2], b0.z, b0.z);
            PACK2(bb[3], b0.w, b0.w);
            PACK2(bb[4], b1.x, b1.x);
            PACK2(bb[5], b1.y, b1.y);
            PACK2(bb[6], b1.z, b1.z);
            PACK2(bb[7], b1.w, b1.w);
#pragma unroll
            for (int v = 0; v < 8; v++) {
                FMA2(acc2[0][v], a.x, bb[v], acc2[0][v]);
                FMA2(acc2[1][v], a.y, bb[v], acc2[1][v]);
            }
        }
        if (!more) break;
        ch = chn;
        __syncthreads();
    }

    float* prow = g_P + ((size_t)s * ROWS + r0) * C_;
#pragma unroll
    for (int p = 0; p < 2; p++) {
        unsigned lo[8], hi[8];
#pragma unroll
        for (int v = 0; v < 8; v++) UNPACK2(lo[v], hi[v], acc2[p][v]);
        const int ra = ty * 4 + 2 * p;
#pragma unroll
        for (int half = 0; half < 2; half++) {
            float4 o0 = make_float4(
                __uint_as_float(half ? hi[0] : lo[0]),
                __uint_as_float(half ? hi[1] : lo[1]),
                __uint_as_float(half ? hi[2] : lo[2]),
                __uint_as_float(half ? hi[3] : lo[3]));
            float4 o1 = make_float4(
                __uint_as_float(half ? hi[4] : lo[4]),
                __uint_as_float(half ? hi[5] : lo[5]),
                __uint_as_float(half ? hi[6] : lo[6]),
                __uint_as_float(half ? hi[7] : lo[7]));
            *reinterpret_cast<float4*>(&prow[(ra + half) * C_ + tx * 8]) = o0;
            *reinterpret_cast<float4*>(&prow[(ra + half) * C_ + tx * 8 + 4]) = o1;
        }
    }
}

// ---------------------------------------------------------------------------
// Reduce: Xc[row][c] = relu( sum_s P[s][row][c] + X[row]@Wroot + bconv )
// ---------------------------------------------------------------------------
__global__ void __launch_bounds__(128) reduce_kernel(
    const float* __restrict__ obs,
    const float* __restrict__ Wroot,
    const float* __restrict__ bconv) {
    const int row = blockIdx.x;
    const int c = threadIdx.x;
    const int b = row >> 5, j = row & 31;

    float sum = bconv[c];
#pragma unroll
    for (int s = 0; s < KSPLIT; s++)
        sum += g_P[((size_t)s * ROWS + row) * C_ + c];

    const float* xr = obs + (size_t)b * OBS_STRIDE + j * F_;
#pragma unroll
    for (int f = 0; f < F_; f++) sum += xr[f] * Wroot[f * C_ + c];

    g_Xc[(size_t)row * C_ + c] = fmaxf(sum, 0.0f);
}

// ---------------------------------------------------------------------------
// Phase 3: per batch element — attention softmax pool + dense tanh
// ---------------------------------------------------------------------------
__global__ void __launch_bounds__(256) phase3_kernel(
    const float* __restrict__ attn_w,
    const float* __restrict__ Wd,
    const float* __restrict__ bd,
    float* __restrict__ out) {
    __shared__ __align__(16) float Xc[N_][C_];
    __shared__ float attn[N_];
    __shared__ float logits[N_];
    __shared__ float pooled[C_];

    const int b = blockIdx.x;
    const int tid = threadIdx.x;

#pragma unroll
    for (int l = 0; l < 4; l++) {
        int t = tid + l * 256;
        reinterpret_cast<float4*>(&Xc[0][0])[t] =
            reinterpret_cast<const float4*>(g_Xc + (size_t)b * N_ * C_)[t];
    }
    __syncthreads();

    const int w = tid >> 5, lane = tid & 31;
    const float aw0 = attn_w[lane], aw1 = attn_w[lane + 32];
    const float aw2 = attn_w[lane + 64], aw3 = attn_w[lane + 96];
    for (int j = w * 4; j < w * 4 + 4; j++) {
        float p = Xc[j][lane] * aw0 + Xc[j][lane + 32] * aw1 +
                  Xc[j][lane + 64] * aw2 + Xc[j][lane + 96] * aw3;
#pragma unroll
        for (int off = 16; off; off >>= 1) p += __shfl_xor_sync(0xffffffffu, p, off);
        if (lane == 0) logits[j] = p;
    }
    __syncthreads();

    if (tid < 32) {
        float l = logits[tid];
        float m = l;
#pragma unroll
        for (int off = 16; off; off >>= 1)
            m = fmaxf(m, __shfl_xor_sync(0xffffffffu, m, off));
        float e = expf(l - m);
        float ssum = e;
#pragma unroll
        for (int off = 16; off; off >>= 1) ssum += __shfl_xor_sync(0xffffffffu, ssum, off);
        attn[tid] = e / ssum;
    }
    __syncthreads();

    if (tid < C_) {
        float pc = 0.0f;
#pragma unroll
        for (int j = 0; j < N_; j++) pc += attn[j] * Xc[j][tid];
        pooled[tid] = pc;
    }
    __syncthreads();

    float sum = bd[tid];
#pragma unroll 8
    for (int cc = 0; cc < C_; cc++) sum += pooled[cc] * Wd[cc * D_ + tid];
    out[(size_t)b * D_ + tid] = tanhf(sum);
}

// ---------------------------------------------------------------------------
extern "C" void kernel_launch(void* const* d_in, const int* in_sizes, int n_in,
                              void* d_out, int out_size) {
    const float* obs    = (const float*)d_in[0];
    const float* W1     = (const float*)d_in[1];
    const float* b1     = (const float*)d_in[2];
    const float* W2     = (const float*)d_in[3];
    const float* b2     = (const float*)d_in[4];
    const float* Wk     = (const float*)d_in[5];
    const float* bk     = (const float*)d_in[6];
    const float* Wroot  = (const float*)d_in[7];
    const float* bconv  = (const float*)d_in[8];
    const float* attn_w = (const float*)d_in[9];
    const float* Wd     = (const float*)d_in[10];
    const float* bd     = (const float*)d_in[11];
    float* out = (float*)d_out;

    prep_kernel<<<(KAUG * C_ + 255) / 256, 256>>>(Wk, bk);
    phase1_kernel<<<ROWS, 256>>>(obs, W1, b1, W2, b2);
    gemm_kernel<<<dim3(ROWS / 64, KSPLIT), 256>>>();
    reduce_kernel<<<ROWS, 128>>>(obs, Wroot, bconv);
    phase3_kernel<<<B_, 256>>>(attn_w, Wd, bd, out);
}